// round 15
// baseline (speedup 1.0000x reference)
#include <cuda_runtime.h>

#define NH 192            // nH = nW = 193 - 2 + 1
#define HG 193            // grid H/W
#define MD 64             // vec dim m

// Scratch (allocation-free rule: __device__ globals)
__device__ float g_x[NH * NH * MD];      // x = win_avg(grid) @ M^T, 9.4 MB

// ---- packed f32x2 helpers -------------------------------------------------
__device__ __forceinline__ unsigned long long pk(float x, float y) {
    unsigned long long r;
    asm("mov.b64 %0, {%1, %2};" : "=l"(r) : "f"(x), "f"(y));
    return r;
}
__device__ __forceinline__ float2 upk(unsigned long long v) {
    float2 t;
    asm("mov.b64 {%0, %1}, %2;" : "=f"(t.x), "=f"(t.y) : "l"(v));
    return t;
}
__device__ __forceinline__ unsigned long long fma2(unsigned long long a,
                                                   unsigned long long b,
                                                   unsigned long long c) {
    unsigned long long r;
    asm("fma.rn.f32x2 %0, %1, %2, %3;" : "=l"(r) : "l"(a), "l"(b), "l"(c));
    return r;
}

// ---- cp.async helpers -------------------------------------------------------
__device__ __forceinline__ void cp_async16(unsigned dst_smem, const void* src) {
    asm volatile("cp.async.cg.shared.global [%0], [%1], 16;"
                 :: "r"(dst_smem), "l"(src) : "memory");
}
__device__ __forceinline__ void cp_commit() {
    asm volatile("cp.async.commit_group;" ::: "memory");
}
template <int N>
__device__ __forceinline__ void cp_wait() {
    asm volatile("cp.async.wait_group %0;" :: "n"(N) : "memory");
}

// ---------------------------------------------------------------------------
// Kernel 1: x[b, j] = sum_l wavg[b, l] * M[j, l]   (proven)
// ---------------------------------------------------------------------------
__global__ void __launch_bounds__(256) x_prep(const float* __restrict__ grid,
                                              const float* __restrict__ Mw) {
    __shared__ __align__(16) float sbuf[66 * 64];

    int t  = threadIdx.x;
    int q  = t >> 6;
    int jl = t & 63;

    int bid    = blockIdx.x;
    int k1     = bid / 6;
    int k2base = (bid % 6) * 32;

    for (int e = t; e < 4096; e += 256) sbuf[(e >> 6) * 66 + (e & 63)] = Mw[e];
    __syncthreads();
    unsigned long long Mp[32];
#pragma unroll
    for (int l = 0; l < 32; l++)
        Mp[l] = pk(sbuf[jl * 66 + 2 * l], sbuf[jl * 66 + 2 * l + 1]);
    __syncthreads();

#pragma unroll
    for (int r = 0; r < 8; r++) {
        int e   = t + 256 * r;
        int row = e >> 6;
        int col = e & 63;
        const float* g00 = grid + ((k1 * HG + k2base + row) * MD) + col;
        sbuf[row * 64 + col] = 0.25f * (g00[0] + g00[MD] +
                                        g00[HG * MD] + g00[HG * MD + MD]);
    }
    __syncthreads();

#pragma unroll
    for (int r = 0; r < 8; r++) {
        int k2r = q + 4 * r;
        const ulonglong2* w2 = reinterpret_cast<const ulonglong2*>(&sbuf[k2r * 64]);
        unsigned long long a0 = 0ULL, a1 = 0ULL;
#pragma unroll
        for (int l = 0; l < 16; l++) {
            ulonglong2 w = w2[l];
            a0 = fma2(Mp[2 * l],     w.x, a0);
            a1 = fma2(Mp[2 * l + 1], w.y, a1);
        }
        float2 f0 = upk(a0), f1 = upk(a1);
        g_x[(k1 * NH + k2base + k2r) * MD + jl] = (f0.x + f0.y) + (f1.x + f1.y);
    }
}

// ---------------------------------------------------------------------------
// Main kernel — DOUBLE-STEP Chebyshev with PERIOD-8 sign folding (pure FMA):
//   d_{k+2} = 2cos(2theta)*d_k - d_{k-2}
//   eps_k: +1 for k mod 8 in {0..3}, -1 for {4..7}  (eps_{k+4} = -eps_k)
//   u_k = eps_k * d_k  ==>  u_{k+2} = s(k)*2cos(2theta)*u_k + u_{k-2}
//   where s(k) = +1 for k mod 4 in {0,1}, -1 for {2,3}  (compile-time!)
//   -> recurrence is ONE fma2 per j-pair, constants C+ / C- chosen statically.
//   Output at step k: true = eps_k * part; eps = (+,+,+,+,-,-,-,-) -> sign per
//   4-step group alternates +,-,+,- (16-blocks repeat: 16 = 0 mod 8).
//   Verified by hand: u2=c2, u4=-c4, u6=-c6, u8=+c8.  (R14 used one constant
//   for all steps -> unstable root -> 1.8e11 blowup. This fixes exactly that.)
//
// 256 threads = (i 0..63) x (jq 0..3); thread owns 16 j values.
// State: C+[8], C-[8], Ecur/Eold/Ocur/Oold[8 each] = 48 ull = 96 regs.
// __launch_bounds__(256, 2) -> 2 CTAs/SM.  CTA = 1 k1 x 64 k2.
// Grid (3 k2-chunks, 192 k1) = 576 CTAs ~= 2 waves.
// x staged in 16-k2 blocks via cp.async double buffer (proven pattern).
// ---------------------------------------------------------------------------
__global__ void __launch_bounds__(256, 2) main_kernel(const float* __restrict__ P,
                                                      float* __restrict__ out) {
    __shared__ __align__(16) float xs[2][16][64];        // 8 KB

    int t   = threadIdx.x;
    int jq  = t & 3;                    // 16-j slice
    int i   = t >> 2;                   // 0..63
    int k1  = blockIdx.y;
    int k2s = blockIdx.x * 64;          // multiple of 64 -> k2s mod 8 == 0

    unsigned xs_base = (unsigned)__cvta_generic_to_shared(&xs[0][0][0]);

    // stage one 16-k2 block of x: 256 float4s, exactly one per thread
    auto issue_block = [&](int b) {
        int kb = k2s + b * 16;
        unsigned dbase = xs_base + ((b & 1) ? 4096u : 0u);
        int r  = t >> 4;                             // k2 offset 0..15
        int j4 = t & 15;
        const float4* src = reinterpret_cast<const float4*>(g_x) +
                            ((k1 * NH + kb + r) << 4) + j4;
        unsigned dst = dbase + ((r * 64 + j4 * 4) << 2);
        cp_async16(dst, src);
        cp_commit();
    };

    issue_block(0);          // overlap staging with the cosf-heavy prologue
    issue_block(1);

    // ---- prologue: inline cos; build constants and 4 chain states ----
    unsigned long long CP[8], CN[8], Ecur[8], Eold[8], Ocur[8], Oold[8];
    {
        const float TWO_PI = 6.2831853071795864769f;
        float k1f = (float)k1;
        float f0  = (float)k2s;          // even chain current   (eps=+: 0 mod 8)
        float f2  = (float)(k2s - 2);    // even chain older     (eps=-: 6 mod 8)
        float f1  = (float)(k2s + 1);    // odd chain current    (eps=+: 1 mod 8)
        float f3  = (float)(k2s - 1);    // odd chain older      (eps=-: 7 mod 8)
        int   jb  = jq * 16;
#pragma unroll
        for (int p = 0; p < 4; p++) {
            float4 pp = reinterpret_cast<const float4*>(P)[i * 16 + jq * 4 + p];
            float pv[4] = {pp.x, pp.y, pp.z, pp.w};
            float ea[4], eb[4], oa[4], ob[4], cp_[4];
#pragma unroll
            for (int c = 0; c < 4; c++) {
                float Tj  = (float)(i * MD + jb + p * 4 + c + 2);
                float w   = TWO_PI / Tj;
                float e   = cosf(w * k1f) * pv[c];     // E = P * cos1
                ea[c] =  e * cosf(w * f0);             // u_{k2s}
                eb[c] = -e * cosf(w * f2);             // u_{k2s-2}
                oa[c] =  e * cosf(w * f1);             // u_{k2s+1}
                ob[c] = -e * cosf(w * f3);             // u_{k2s-1}
                cp_[c] = 2.0f * cosf(2.0f * w);        // +2cos(2theta)
            }
            Ecur[2*p] = pk(ea[0], ea[1]);  Ecur[2*p+1] = pk(ea[2], ea[3]);
            Eold[2*p] = pk(eb[0], eb[1]);  Eold[2*p+1] = pk(eb[2], eb[3]);
            Ocur[2*p] = pk(oa[0], oa[1]);  Ocur[2*p+1] = pk(oa[2], oa[3]);
            Oold[2*p] = pk(ob[0], ob[1]);  Oold[2*p+1] = pk(ob[2], ob[3]);
            CP[2*p]   = pk(cp_[0], cp_[1]);
            CP[2*p+1] = pk(cp_[2], cp_[3]);
            CN[2*p]   = pk(-cp_[0], -cp_[1]);
            CN[2*p+1] = pk(-cp_[2], -cp_[3]);
        }
    }

    float* obase = out + (k1 * NH + k2s) * MD + i;

    // one k2 step: accumulate with chain-current C, advance D = fma(K, C, D)
#define STEP(C, D, K, SGNF, ROFF, XB)                                       \
    {                                                                       \
        const ulonglong2* xr =                                              \
            reinterpret_cast<const ulonglong2*>((XB) + (ROFF) * 64);        \
        unsigned long long a0 = 0ULL, a1 = 0ULL;                            \
        _Pragma("unroll")                                                   \
        for (int p = 0; p < 4; p++) {                                       \
            ulonglong2 xv = xr[p];                                          \
            a0 = fma2(C[2 * p],     xv.x, a0);                              \
            a1 = fma2(C[2 * p + 1], xv.y, a1);                              \
        }                                                                   \
        _Pragma("unroll")                                                   \
        for (int p = 0; p < 8; p++) D[p] = fma2(K[p], C[p], D[p]);          \
        float2 q0 = upk(a0), q1 = upk(a1);                                  \
        float part = (q0.x + q0.y) + (q1.x + q1.y);                         \
        part += __shfl_xor_sync(0xFFFFFFFFu, part, 1);                      \
        part += __shfl_xor_sync(0xFFFFFFFFu, part, 2);                      \
        if (jq == 0) obase[(b * 16 + (ROFF)) * MD] = SGNF(part);            \
    }
#define POSF(x) (x)
#define NEGF(x) (-(x))

    // ---- main loop: 4 blocks x 16 k2 ----
    for (int b = 0; b < 4; b++) {
        if (b >= 1) {
            __syncthreads();             // readers of buf[(b+1)&1] (block b-1) done
            if (b + 1 < 4) issue_block(b + 1);
        }
        if (b + 1 < 4) cp_wait<1>(); else cp_wait<0>();
        __syncthreads();                 // block b visible to all

        const float* xb = &xs[b & 1][0][jq * 16];

        // group g covers k offsets 4g..4g+3; store sign eps = +,-,+,- per group;
        // recurrence constant: CP for k mod 4 in {0,1}, CN for {2,3}
        // g = 0 (k mod 8 = 0..3, eps = +)
        STEP(Ecur, Eold, CP, POSF,  0, xb)
        STEP(Ocur, Oold, CP, POSF,  1, xb)
        STEP(Eold, Ecur, CN, POSF,  2, xb)
        STEP(Oold, Ocur, CN, POSF,  3, xb)
        // g = 1 (k mod 8 = 4..7, eps = -)
        STEP(Ecur, Eold, CP, NEGF,  4, xb)
        STEP(Ocur, Oold, CP, NEGF,  5, xb)
        STEP(Eold, Ecur, CN, NEGF,  6, xb)
        STEP(Oold, Ocur, CN, NEGF,  7, xb)
        // g = 2 (eps = +)
        STEP(Ecur, Eold, CP, POSF,  8, xb)
        STEP(Ocur, Oold, CP, POSF,  9, xb)
        STEP(Eold, Ecur, CN, POSF, 10, xb)
        STEP(Oold, Ocur, CN, POSF, 11, xb)
        // g = 3 (eps = -)
        STEP(Ecur, Eold, CP, NEGF, 12, xb)
        STEP(Ocur, Oold, CP, NEGF, 13, xb)
        STEP(Eold, Ecur, CN, NEGF, 14, xb)
        STEP(Oold, Ocur, CN, NEGF, 15, xb)
    }
#undef STEP
#undef POSF
#undef NEGF
}

// ---------------------------------------------------------------------------
// Launch: inputs in metadata order: grid [193,193,64], M_weight [64,64], P [64,64]
// ---------------------------------------------------------------------------
extern "C" void kernel_launch(void* const* d_in, const int* in_sizes, int n_in,
                              void* d_out, int out_size) {
    const float* grid = (const float*)d_in[0];
    const float* Mw   = (const float*)d_in[1];
    const float* P    = (const float*)d_in[2];
    float* out        = (float*)d_out;

    x_prep<<<1152, 256>>>(grid, Mw);
    main_kernel<<<dim3(3, 192), 256>>>(P, out);
}

// round 16
// speedup vs baseline: 1.3629x; 1.3629x over previous
#include <cuda_runtime.h>

#define NH 192            // nH = nW = 193 - 2 + 1
#define HG 193            // grid H/W
#define MD 64             // vec dim m

// Scratch (allocation-free rule: __device__ globals)
__device__ float g_x[NH * NH * MD];      // x = win_avg(grid) @ M^T, 9.4 MB

// ---- packed f32x2 helpers (used only in x_prep, which is proven) -----------
__device__ __forceinline__ unsigned long long pk(float x, float y) {
    unsigned long long r;
    asm("mov.b64 %0, {%1, %2};" : "=l"(r) : "f"(x), "f"(y));
    return r;
}
__device__ __forceinline__ float2 upk(unsigned long long v) {
    float2 t;
    asm("mov.b64 {%0, %1}, %2;" : "=f"(t.x), "=f"(t.y) : "l"(v));
    return t;
}
__device__ __forceinline__ unsigned long long fma2(unsigned long long a,
                                                   unsigned long long b,
                                                   unsigned long long c) {
    unsigned long long r;
    asm("fma.rn.f32x2 %0, %1, %2, %3;" : "=l"(r) : "l"(a), "l"(b), "l"(c));
    return r;
}

// ---- cp.async helpers -------------------------------------------------------
__device__ __forceinline__ void cp_async16(unsigned dst_smem, const void* src) {
    asm volatile("cp.async.cg.shared.global [%0], [%1], 16;"
                 :: "r"(dst_smem), "l"(src) : "memory");
}
__device__ __forceinline__ void cp_commit() {
    asm volatile("cp.async.commit_group;" ::: "memory");
}
template <int N>
__device__ __forceinline__ void cp_wait() {
    asm volatile("cp.async.wait_group %0;" :: "n"(N) : "memory");
}

// ---------------------------------------------------------------------------
// Kernel 1: x[b, j] = sum_l wavg[b, l] * M[j, l]   (R9 version — proven ~7us)
// ---------------------------------------------------------------------------
__global__ void __launch_bounds__(256) x_prep(const float* __restrict__ grid,
                                              const float* __restrict__ Mw) {
    __shared__ __align__(16) float sbuf[66 * 64];

    int t  = threadIdx.x;
    int q  = t >> 6;
    int jl = t & 63;

    int bid    = blockIdx.x;
    int k1     = bid / 6;
    int k2base = (bid % 6) * 32;

    for (int e = t; e < 4096; e += 256) sbuf[(e >> 6) * 66 + (e & 63)] = Mw[e];
    __syncthreads();
    unsigned long long Mp[32];
#pragma unroll
    for (int l = 0; l < 32; l++)
        Mp[l] = pk(sbuf[jl * 66 + 2 * l], sbuf[jl * 66 + 2 * l + 1]);
    __syncthreads();

#pragma unroll
    for (int r = 0; r < 8; r++) {
        int e   = t + 256 * r;
        int row = e >> 6;
        int col = e & 63;
        const float* g00 = grid + ((k1 * HG + k2base + row) * MD) + col;
        sbuf[row * 64 + col] = 0.25f * (g00[0] + g00[MD] +
                                        g00[HG * MD] + g00[HG * MD + MD]);
    }
    __syncthreads();

#pragma unroll
    for (int r = 0; r < 8; r++) {
        int k2r = q + 4 * r;
        const ulonglong2* w2 = reinterpret_cast<const ulonglong2*>(&sbuf[k2r * 64]);
        unsigned long long a0 = 0ULL, a1 = 0ULL;
#pragma unroll
        for (int l = 0; l < 16; l++) {
            ulonglong2 w = w2[l];
            a0 = fma2(Mp[2 * l],     w.x, a0);
            a1 = fma2(Mp[2 * l + 1], w.y, a1);
        }
        float2 f0 = upk(a0), f1 = upk(a1);
        g_x[(k1 * NH + k2base + k2r) * MD + jl] = (f0.x + f0.y) + (f1.x + f1.y);
    }
}

// ---------------------------------------------------------------------------
// Main kernel — SCALAR Chebyshev (no f32x2, no XOR, no MOV bloat):
//   d_{k+1} = tc*d_k - d_{k-1},  tc = 2cos(theta)
//   2-step ping-pong:  B = fmaf(tc, A, -B);  A = fmaf(tc, B, -A);
//   (the -operand is a free FFMA modifier in SASS; zero copies)
//
// R13's PROVEN skeleton: 512 threads = (k1sub 0..1) x (i 0..63) x (jq 0..3),
// 16 j per thread; __launch_bounds__(512,2) -> 2 CTAs/SM = 32 warps/SM.
// CTA = 2 k1 x 64 k2; grid (3, 96) = 288 CTAs = ONE wave.
// State: tc[16] + A[16] + B[16] = 48 scalar regs (fits 64-reg cap).
// x staged in 16-k2 blocks via cp.async double buffer (proven pattern).
// jq lanes reduced with 2 shfl_xor; jq==0 lane stores (32B-coalesced).
// ---------------------------------------------------------------------------
__global__ void __launch_bounds__(512, 2) main_kernel(const float* __restrict__ P,
                                                      float* __restrict__ out) {
    __shared__ __align__(16) float xs[2][16][2][64];     // 16 KB

    int t      = threadIdx.x;
    int jq     = t & 3;                  // 16-j slice
    int i      = (t >> 2) & 63;
    int k1sub  = t >> 8;                 // 0..1
    int k1base = blockIdx.y * 2;
    int k1     = k1base + k1sub;
    int k2s    = blockIdx.x * 64;

    unsigned xs_base = (unsigned)__cvta_generic_to_shared(&xs[0][0][0][0]);

    // stage one 16-k2 block of x: 512 float4s, exactly one per thread (proven)
    auto issue_block = [&](int b) {
        int kb = k2s + b * 16;
        unsigned dbase = xs_base + ((b & 1) ? 8192u : 0u);
        int s  = t >> 8;                             // k1 row 0..1
        int r  = (t >> 4) & 15;                      // k2 offset 0..15
        int j4 = t & 15;
        const float4* src = reinterpret_cast<const float4*>(g_x) +
                            (((k1base + s) * NH + kb + r) << 4) + j4;
        unsigned dst = dbase + (((r * 2 + s) * 64 + j4 * 4) << 2);
        cp_async16(dst, src);
        cp_commit();
    };

    issue_block(0);          // overlap staging with the cosf-heavy prologue
    issue_block(1);

    // ---- prologue: inline cos; build tc / A / B for this thread's 16 j ----
    float tc[16], A[16], B[16];
    {
        const float TWO_PI = 6.2831853071795864769f;
        float k1f = (float)k1;
        float kaf = (float)k2s;
        float kbf = (float)(k2s - 1);                // cosf even: d_{-1} = d_1
        int   jb  = jq * 16;
#pragma unroll
        for (int c = 0; c < 16; c++) {
            float Tj = (float)(i * MD + jb + c + 2);
            float w  = TWO_PI / Tj;
            float e  = cosf(w * k1f) * P[i * MD + jb + c];   // E = P * cos1
            A[c]  = e * cosf(w * kaf);               // d_{k2s}
            B[c]  = e * cosf(w * kbf);               // d_{k2s-1}
            tc[c] = 2.0f * cosf(w);                  // 2 cos(theta)
        }
    }

    float* obase = out + (k1 * NH + k2s) * MD + i;

    // one k2 step: accumulate with chain C, advance other chain D = tc*C - D
#define STEP(C, D, ROFF, XB)                                                \
    {                                                                       \
        const float4* xr =                                                  \
            reinterpret_cast<const float4*>((XB) + (ROFF) * 128);           \
        float a0 = 0.f, a1 = 0.f;                                           \
        _Pragma("unroll")                                                   \
        for (int h = 0; h < 2; h++) {                                       \
            float4 x0 = xr[2 * h];                                          \
            float4 x1 = xr[2 * h + 1];                                      \
            a0 = fmaf(C[8 * h + 0], x0.x, a0);                              \
            a1 = fmaf(C[8 * h + 1], x0.y, a1);                              \
            a0 = fmaf(C[8 * h + 2], x0.z, a0);                              \
            a1 = fmaf(C[8 * h + 3], x0.w, a1);                              \
            a0 = fmaf(C[8 * h + 4], x1.x, a0);                              \
            a1 = fmaf(C[8 * h + 5], x1.y, a1);                              \
            a0 = fmaf(C[8 * h + 6], x1.z, a0);                              \
            a1 = fmaf(C[8 * h + 7], x1.w, a1);                              \
        }                                                                   \
        _Pragma("unroll")                                                   \
        for (int c = 0; c < 16; c++) D[c] = fmaf(tc[c], C[c], -D[c]);       \
        float part = a0 + a1;                                               \
        part += __shfl_xor_sync(0xFFFFFFFFu, part, 1);                      \
        part += __shfl_xor_sync(0xFFFFFFFFu, part, 2);                      \
        if (jq == 0) obase[(b * 16 + (ROFF)) * MD] = part;                  \
    }

    // ---- main loop: 4 blocks x 16 k2 (2-step ping-pong, zero copies) ----
    for (int b = 0; b < 4; b++) {
        if (b >= 1) {
            __syncthreads();             // readers of buf[(b+1)&1] (block b-1) done
            if (b + 1 < 4) issue_block(b + 1);
        }
        if (b + 1 < 4) cp_wait<1>(); else cp_wait<0>();
        __syncthreads();                 // block b visible to all

        const float* xb = &xs[b & 1][0][k1sub][jq * 16];

#pragma unroll
        for (int r = 0; r < 8; r++) {
            STEP(A, B, 2 * r,     xb)    // acc d_k;    B <- d_{k+1}
            STEP(B, A, 2 * r + 1, xb)    // acc d_{k+1}; A <- d_{k+2}
        }
    }
#undef STEP
}

// ---------------------------------------------------------------------------
// Launch: inputs in metadata order: grid [193,193,64], M_weight [64,64], P [64,64]
// ---------------------------------------------------------------------------
extern "C" void kernel_launch(void* const* d_in, const int* in_sizes, int n_in,
                              void* d_out, int out_size) {
    const float* grid = (const float*)d_in[0];
    const float* Mw   = (const float*)d_in[1];
    const float* P    = (const float*)d_in[2];
    float* out        = (float*)d_out;

    x_prep<<<1152, 256>>>(grid, Mw);
    main_kernel<<<dim3(3, 96), 512>>>(P, out);
}